// round 16
// baseline (speedup 1.0000x reference)
#include <cuda_runtime.h>
#include <cstdint>

#define NB 64
#define NN 1024
#define DD 128
#define KK 6
#define NCX 16
#define NCELL 256
#define CW (1.0f / 16.0f)
#define KNN_BLOCKS (NB * 2)   // 128: two blocks per batch; 512 queries x 2 roles

// Scratch (device globals: no allocation allowed)
__device__ int   g_nbr[NB * NN * KK];     // 1.5 MB: neighbor indices
__device__ float g_P[KK * DD];
__device__ float g_Q[KK * DD];
__device__ float g_R[KK * DD];
__device__ float g_part[512 * DD];        // per-gather-block mean partials

// ---------------------------------------------------------------------------
// K1 (fused): blocks [0,128): exact kNN, 2 blocks/batch, 1024 threads,
//   2 threads per query (role 0/1 split candidate cells alternately, each
//   keeps an exact partial top-6; role 0 merges -> exact global top-6).
//             blocks [128,134): weight collapse P/Q/R[k,d] (tid<256 active).
// ---------------------------------------------------------------------------
__global__ __launch_bounds__(1024, 1)
void k_knn_weights(const float* __restrict__ loc,
                   const float* __restrict__ W2d,
                   const float* __restrict__ b2d,
                   const float* __restrict__ Wnb) {
    const int tid = threadIdx.x;

    if (blockIdx.x >= KNN_BLOCKS) {
        // ============ weights path: one k per block (validated R12) ========
        __shared__ float w0s[128], w1s[128], bs[128];
        __shared__ float pa[128], qa[128], ra[128];
        const int k = blockIdx.x - KNN_BLOCKS;
        const int d = tid >> 1, half = tid & 1;
        float p = 0.f, q = 0.f, r = 0.f;

        if (tid < 128) {
            w0s[tid] = W2d[tid * 2 + 0];
            w1s[tid] = W2d[tid * 2 + 1];
            bs[tid]  = b2d[tid];
        }
        __syncthreads();

        if (tid < 256) {
            const float* wrow = Wnb + d * (KK * DD) + k * DD + half * 64;
#pragma unroll 8
            for (int i = 0; i < 64; i++) {
                float wv = __ldg(wrow + i);
                int dd = half * 64 + i;
                p = fmaf(w0s[dd], wv, p);
                q = fmaf(w1s[dd], wv, q);
                r = fmaf(bs[dd],  wv, r);
            }
            if (half) { pa[d] = p; qa[d] = q; ra[d] = r; }
        }
        __syncthreads();
        if (tid < 256 && !half) {
            g_P[k * DD + d] = p + pa[d];
            g_Q[k * DD + d] = q + qa[d];
            g_R[k * DD + d] = r + ra[d];
        }
        return;
    }

    // ============ kNN path ============
    __shared__ float2 ps[NN];
    __shared__ short  js[NN];
    __shared__ unsigned short cnt2[NCELL][32];   // [cell][warp j-block] bases
    __shared__ int cntTot[NCELL];
    __shared__ int cstart[NCELL];
    __shared__ unsigned long long mbuf[512][KK]; // role-1 partial top-6

    const int b = blockIdx.x >> 1;
    const int halfsel = blockIdx.x & 1;          // which 512 sorted positions
    const int w = tid >> 5, l = tid & 31;
    const unsigned lmask = (1u << l) - 1u;

    // Zero per-(cell,warp) histogram.
    for (int i = tid; i < NCELL * 32 / 2; i += 1024)
        ((unsigned*)cnt2)[i] = 0u;

    // Load 1 point per thread (j = tid); keep in registers.
    const float2* locb = (const float2*)(loc + (size_t)b * NN * 2);
    float2 myp = locb[tid];
    int myc;
    {
        int cx = (int)(myp.x * 16.0f); cx = cx < 0 ? 0 : (cx > 15 ? 15 : cx);
        int cy = (int)(myp.y * 16.0f); cy = cy < 0 ? 0 : (cy > 15 ? 15 : cy);
        myc = cy * NCX + cx;
    }
    __syncthreads();

    // Per-(cell, warp) histogram via match leaders (warp w = j-block w).
    {
        unsigned mask = __match_any_sync(0xffffffffu, myc);
        if ((mask & lmask) == 0) cnt2[myc][w] = (unsigned short)__popc(mask);
    }
    __syncthreads();

    // Per-cell prefix over 32 warp-blocks (thread c = cell c).
    if (tid < NCELL) {
        int run = 0;
#pragma unroll
        for (int ww = 0; ww < 32; ww++) {
            int t = cnt2[tid][ww];
            cnt2[tid][ww] = (unsigned short)run;
            run += t;
        }
        cntTot[tid] = run;
    }
    __syncthreads();

    // Exclusive prefix over 256 cells by warp 0 (8 cells/lane).
    if (tid < 32) {
        int base = tid * 8;
        int c8[8]; int T = 0;
#pragma unroll
        for (int i = 0; i < 8; i++) { c8[i] = cntTot[base + i]; T += c8[i]; }
        int incl = T;
#pragma unroll
        for (int off = 1; off < 32; off <<= 1) {
            int v = __shfl_up_sync(0xffffffffu, incl, off);
            if (tid >= off) incl += v;
        }
        int run = incl - T;
#pragma unroll
        for (int i = 0; i < 8; i++) { cstart[base + i] = run; run += c8[i]; }
    }
    __syncthreads();

    // Deterministic parallel scatter, j-ascending within each cell.
    {
        unsigned mask = __match_any_sync(0xffffffffu, myc);
        int rank = __popc(mask & lmask);
        int pos = cstart[myc] + (int)cnt2[myc][w] + rank;
        ps[pos] = myp;
        js[pos] = (short)tid;
    }
    __syncthreads();

    // 2 threads per query: qidx = tid & 511, role = tid >> 9.
    const int qidx = tid & 511;
    const int role = tid >> 9;
    const int sp = halfsel * 512 + qidx;
    const float2 qpt = ps[sp];
    const int n = js[sp];
    const float qx = qpt.x, qy = qpt.y;

    const unsigned long long KINIT =
        (((unsigned long long)0x7f800000u) << 32) | 0xffffffffull;
    unsigned long long k0 = KINIT, k1 = KINIT, k2 = KINIT,
                       k3 = KINIT, k4 = KINIT, k5 = KINIT;
    unsigned bd5u = 0x7f800000u;

#define INSERT_KEY(key_)                                                     \
    if (key_ < k5) {                                                         \
        bool c4 = key_ < k4, c3 = key_ < k3, c2 = key_ < k2,                 \
             c1_ = key_ < k1, c0_ = key_ < k0;                               \
        k5 = c4 ? k4 : key_;                                                 \
        k4 = c4 ? (c3 ? k3 : key_) : k4;                                     \
        k3 = c3 ? (c2 ? k2 : key_) : k3;                                     \
        k2 = c2 ? (c1_ ? k1 : key_) : k2;                                    \
        k1 = c1_ ? (c0_ ? k0 : key_) : k1;                                   \
        k0 = c0_ ? key_ : k0;                                                \
        bd5u = (unsigned)(k5 >> 32);                                         \
    }

#define PROC_CELL(c)                                                         \
    {                                                                        \
        int s_ = cstart[c];                                                  \
        int e_ = s_ + cntTot[c];                                             \
        for (int i_ = s_; i_ < e_; i_++) {                                   \
            float2 p_ = ps[i_];                                              \
            float dx_ = p_.x - qx;                                           \
            float dy_ = p_.y - qy;                                           \
            float d2_ = fmaf(dx_, dx_, dy_ * dy_);                           \
            unsigned d2u_ = __float_as_uint(d2_);                            \
            if (d2u_ <= bd5u) {                                              \
                unsigned long long key_ =                                    \
                    (((unsigned long long)d2u_) << 32) |                     \
                    (unsigned)(unsigned short)js[i_];                        \
                INSERT_KEY(key_)                                             \
            }                                                                \
        }                                                                    \
    }

// Walk-position counter 'wt' assigns cells alternately to roles; assignment
// depends only on the fixed walk order (never on bd5) -> roles consistent.
#define CHECK_PROC(ci, cj)                                                   \
    {                                                                        \
        if ((wt & 1) == role) {                                              \
            float dxm_ = fmaxf(0.f, fmaxf((ci) * CW - qx, qx - ((ci) + 1) * CW));\
            float dym_ = fmaxf(0.f, fmaxf((cj) * CW - qy, qy - ((cj) + 1) * CW));\
            float bd_ = __uint_as_float(bd5u);                               \
            if (fmaf(dxm_, dxm_, dym_ * dym_) <= bd_) PROC_CELL((cj) * NCX + (ci));\
        }                                                                    \
        wt++;                                                                \
    }

    int cx = (int)(qx * 16.0f); cx = cx < 0 ? 0 : (cx > 15 ? 15 : cx);
    int cy = (int)(qy * 16.0f); cy = cy < 0 ? 0 : (cy > 15 ? 15 : cy);

    int wt = 0;
    if (role == 0) PROC_CELL(cy * NCX + cx);
    wt = 1;

    for (int r = 1; r < 16; r++) {
        float dmin = (r - 1) * CW;
        float bd5 = __uint_as_float(bd5u);
        if (dmin * dmin > bd5) break;    // safe per-role (see theory)

        int ci0 = cx - r < 0 ? 0 : cx - r;
        int ci1 = cx + r > 15 ? 15 : cx + r;
        if (cy - r >= 0) {
            int cj = cy - r;
            for (int ci = ci0; ci <= ci1; ci++) CHECK_PROC(ci, cj);
        }
        if (cy + r <= 15) {
            int cj = cy + r;
            for (int ci = ci0; ci <= ci1; ci++) CHECK_PROC(ci, cj);
        }
        int cj0 = cy - r + 1 < 0 ? 0 : cy - r + 1;
        int cj1 = cy + r - 1 > 15 ? 15 : cy + r - 1;
        if (cx - r >= 0) {
            int ci = cx - r;
            for (int cj = cj0; cj <= cj1; cj++) CHECK_PROC(ci, cj);
        }
        if (cx + r <= 15) {
            int ci = cx + r;
            for (int cj = cj0; cj <= cj1; cj++) CHECK_PROC(ci, cj);
        }
    }
#undef CHECK_PROC

    // Role 1 publishes its partial top-6; role 0 merges and writes.
    if (role == 1) {
        mbuf[qidx][0] = k0; mbuf[qidx][1] = k1; mbuf[qidx][2] = k2;
        mbuf[qidx][3] = k3; mbuf[qidx][4] = k4; mbuf[qidx][5] = k5;
    }
    __syncthreads();
    if (role == 0) {
#pragma unroll
        for (int m = 0; m < KK; m++) {
            unsigned long long key_ = mbuf[qidx][m];
            unsigned d2u_ = (unsigned)(key_ >> 32);
            if (d2u_ <= bd5u) { INSERT_KEY(key_) }
        }
        int obase = (b * NN + n) * KK;
        g_nbr[obase + 0] = (int)(k0 & 0xffffffffu);
        g_nbr[obase + 1] = (int)(k1 & 0xffffffffu);
        g_nbr[obase + 2] = (int)(k2 & 0xffffffffu);
        g_nbr[obase + 3] = (int)(k3 & 0xffffffffu);
        g_nbr[obase + 4] = (int)(k4 & 0xffffffffu);
        g_nbr[obase + 5] = (int)(k5 & 0xffffffffu);
    }
#undef PROC_CELL
#undef INSERT_KEY
}

// ---------------------------------------------------------------------------
// K2: Fn = C + sum_k (x_jk*P[k] + y_jk*Q[k]);  + F3 + leaky; write h;
// block mean partials. grid = 512 x 256; warp handles 16 rows.
// ---------------------------------------------------------------------------
__global__ __launch_bounds__(256)
void k_gather(const float* __restrict__ loc,
              const float* __restrict__ deadline,
              const float* __restrict__ W3d,
              const float* __restrict__ b3d,
              const float* __restrict__ bnb,
              float* __restrict__ h) {
    __shared__ float2 loc0[NN];
    __shared__ float red[8][128];
    const int tid = threadIdx.x;
    const int w = tid >> 5, l = tid & 31;

    for (int i = tid; i < NN; i += 256) loc0[i] = ((const float2*)loc)[i];

    float4 P4[KK], Q4[KK], C4;
    C4 = __ldg((const float4*)bnb + l);
#pragma unroll
    for (int k = 0; k < KK; k++) {
        P4[k] = __ldg((const float4*)(g_P + k * DD) + l);
        Q4[k] = __ldg((const float4*)(g_Q + k * DD) + l);
        float4 r4 = __ldg((const float4*)(g_R + k * DD) + l);
        C4.x += r4.x; C4.y += r4.y; C4.z += r4.z; C4.w += r4.w;
    }
    float w3[4][3], b3v[4];
#pragma unroll
    for (int q = 0; q < 4; q++) {
        int d = 4 * l + q;
        w3[q][0] = __ldg(W3d + d * 3 + 0);
        w3[q][1] = __ldg(W3d + d * 3 + 1);
        w3[q][2] = __ldg(W3d + d * 3 + 2);
        b3v[q] = __ldg(b3d + d);
    }
    __syncthreads();

    float4 macc = {0.f, 0.f, 0.f, 0.f};
    const int row0 = blockIdx.x * 128 + w * 16;   // 8 blocks per batch exactly

#pragma unroll 2
    for (int rr = 0; rr < 16; rr++) {
        const int row = row0 + rr;
        const int b = row >> 10, n = row & 1023;

        const int2* nb2 = (const int2*)(g_nbr + (size_t)row * KK);
        int2 i01 = __ldg(nb2 + 0);
        int2 i23 = __ldg(nb2 + 1);
        int2 i45 = __ldg(nb2 + 2);
        int jid[KK] = {i01.x, i01.y, i23.x, i23.y, i45.x, i45.y};

        float4 a = C4;
#pragma unroll
        for (int k = 0; k < KK; k++) {
            float2 pj = loc0[jid[k]];
            a.x = fmaf(pj.x, P4[k].x, fmaf(pj.y, Q4[k].x, a.x));
            a.y = fmaf(pj.x, P4[k].y, fmaf(pj.y, Q4[k].y, a.y));
            a.z = fmaf(pj.x, P4[k].z, fmaf(pj.y, Q4[k].z, a.z));
            a.w = fmaf(pj.x, P4[k].w, fmaf(pj.y, Q4[k].w, a.w));
        }

        float xn = __ldg(loc + (size_t)row * 2 + 0);
        float yn = __ldg(loc + (size_t)row * 2 + 1);
        float tn = __ldg(deadline + row);

        float4 o;
        float* op = (float*)&o;
        const float* ap = (const float*)&a;
#pragma unroll
        for (int q = 0; q < 4; q++) {
            float f3 = fmaf(tn, w3[q][2], fmaf(yn, w3[q][1], fmaf(xn, w3[q][0], b3v[q])));
            float v = ap[q] + f3;
            op[q] = (v >= 0.f) ? v : 0.01f * v;
        }
        ((float4*)(h + ((size_t)(b * (NN + 1) + n + 1)) * DD))[l] = o;
        macc.x += o.x; macc.y += o.y; macc.z += o.z; macc.w += o.w;
    }

    ((float4*)red[w])[l] = macc;
    __syncthreads();
    if (tid < 128) {
        float s = 0.f;
#pragma unroll
        for (int q = 0; q < 8; q++) s += red[q][tid];
        g_part[(size_t)blockIdx.x * DD + tid] = s;
    }
}

// ---------------------------------------------------------------------------
// K3: depot row + mean combine (8 partials/batch). grid = 64, 256 threads.
// ---------------------------------------------------------------------------
__global__ void k_final(const float* __restrict__ depot,
                        const float* __restrict__ Wdep,
                        const float* __restrict__ bdep,
                        float* __restrict__ h,
                        float* __restrict__ mean_out) {
    __shared__ float red[2][128];
    const int b = blockIdx.x;
    const int tid = threadIdx.x;
    const int d = tid & 127, g = tid >> 7;

    float s = 0.f;
    const float* pp = g_part + (size_t)b * 8 * DD;
#pragma unroll
    for (int q = 0; q < 4; q++) s += pp[(size_t)(g * 4 + q) * DD + d];

    if (g == 0) {
        float dep = fmaf(depot[b * 2 + 1], Wdep[d * 2 + 1],
                         fmaf(depot[b * 2 + 0], Wdep[d * 2 + 0], bdep[d]));
        dep = (dep >= 0.f) ? dep : 0.01f * dep;
        h[(size_t)b * (NN + 1) * DD + d] = dep;
        s += dep;
    }
    red[g][d] = s;
    __syncthreads();
    if (g == 0)
        mean_out[b * DD + d] = (red[0][d] + red[1][d]) / 1025.0f;
}

// ---------------------------------------------------------------------------
extern "C" void kernel_launch(void* const* d_in, const int* in_sizes, int n_in,
                              void* d_out, int out_size) {
    const float* loc      = (const float*)d_in[0];
    const float* deadline = (const float*)d_in[1];
    const float* depot    = (const float*)d_in[2];
    const float* W3d      = (const float*)d_in[3];
    const float* b3d      = (const float*)d_in[4];
    const float* W2d      = (const float*)d_in[5];
    const float* b2d      = (const float*)d_in[6];
    const float* Wnb      = (const float*)d_in[7];
    const float* bnb      = (const float*)d_in[8];
    const float* Wdep     = (const float*)d_in[9];
    const float* bdep     = (const float*)d_in[10];

    float* h = (float*)d_out;
    float* mean_out = h + (size_t)NB * (NN + 1) * DD;

    k_knn_weights<<<KNN_BLOCKS + KK, 1024>>>(loc, W2d, b2d, Wnb);
    k_gather<<<512, 256>>>(loc, deadline, W3d, b3d, bnb, h);
    k_final<<<NB, 256>>>(depot, Wdep, bdep, h, mean_out);
}